// round 16
// baseline (speedup 1.0000x reference)
#include <cuda_runtime.h>
#include <cuda_fp16.h>
#include <cstdint>

// Problem: B=2, N=2048, C=1024, H=16, D=64 — fp16 storage, fp32 accumulate.
// g_q/g_k/g_v: half [bh=32][n=2048][128], d 0..63 real, 64..127 imag
// g_z:     half [b*2048+n][2048] = [out_r(1024) | out_i(1024)]
// g_x,g_w: half copies of x and the 6 QKV weights
// g_wc:    half combined output weight; g_fb: fp32 combined bias

#define PROJ_SMEM 73728   // 2 arrays x 2 bufs x 128 rows x 144 B
#define ATT_SMEM  34816   // K 2x8704 + V 2x8704

__device__ __half g_q[32 * 2048 * 128];
__device__ __half g_k[32 * 2048 * 128];
__device__ __half g_v[32 * 2048 * 128];
__device__ __half g_z[4096 * 2048];
__device__ __half g_x[4096 * 1024];
__device__ __half g_w[6 * 1024 * 1024];
__device__ __half g_wc[1024 * 2048];
__device__ float  g_fb[1024];

// ---------------------------------------------------------------------------
// helpers
// ---------------------------------------------------------------------------
__device__ __forceinline__ uint32_t h2pack(float lo, float hi) {
    uint32_t r;
    asm("cvt.rn.f16x2.f32 %0, %1, %2;" : "=r"(r) : "f"(hi), "f"(lo));
    return r;
}
__device__ __forceinline__ float sqrt_ap(float x) {
    float r; asm("sqrt.approx.f32 %0, %1;" : "=f"(r) : "f"(x)); return r;
}
__device__ __forceinline__ float ex2_ap(float x) {
    float r; asm("ex2.approx.f32 %0, %1;" : "=f"(r) : "f"(x)); return r;
}

// m16n8k16 fp16 mma, fp32 accumulate.
__device__ __forceinline__ void mma16(float* d,
                                      uint32_t a0, uint32_t a1, uint32_t a2, uint32_t a3,
                                      uint32_t b0, uint32_t b1) {
    asm volatile(
        "mma.sync.aligned.m16n8k16.row.col.f32.f16.f16.f32 "
        "{%0,%1,%2,%3}, {%4,%5,%6,%7}, {%8,%9}, {%0,%1,%2,%3};"
        : "+f"(d[0]), "+f"(d[1]), "+f"(d[2]), "+f"(d[3])
        : "r"(a0), "r"(a1), "r"(a2), "r"(a3), "r"(b0), "r"(b1));
}

// ldmatrix x4: four 8x8 b16 tiles; lane l supplies the row address for
// tile (l>>3), row (l&7).
__device__ __forceinline__ void ldsm4(uint32_t& r0, uint32_t& r1,
                                      uint32_t& r2, uint32_t& r3, uint32_t addr) {
    asm volatile("ldmatrix.sync.aligned.m8n8.x4.shared.b16 {%0,%1,%2,%3}, [%4];"
                 : "=r"(r0), "=r"(r1), "=r"(r2), "=r"(r3) : "r"(addr));
}
// transposed variant: each 8x8 tile transposed in flight (col-major fragments).
__device__ __forceinline__ void ldsm4t(uint32_t& r0, uint32_t& r1,
                                       uint32_t& r2, uint32_t& r3, uint32_t addr) {
    asm volatile("ldmatrix.sync.aligned.m8n8.x4.trans.shared.b16 {%0,%1,%2,%3}, [%4];"
                 : "=r"(r0), "=r"(r1), "=r"(r2), "=r"(r3) : "r"(addr));
}

__device__ __forceinline__ void cpa16(uint32_t dst, const void* src) {
    asm volatile("cp.async.cg.shared.global [%0], [%1], 16;" :: "r"(dst), "l"(src));
}
#define CP_COMMIT() asm volatile("cp.async.commit_group;")
#define CP_WAIT0()  asm volatile("cp.async.wait_group 0;")

// ---------------------------------------------------------------------------
// Convert x and the 6 QKV weights to fp16 (g_x / g_w).
// ---------------------------------------------------------------------------
__global__ void __launch_bounds__(256) prep_kernel(
    const float* __restrict__ x,
    const float* __restrict__ qrw, const float* __restrict__ qiw,
    const float* __restrict__ krw, const float* __restrict__ kiw,
    const float* __restrict__ vrw, const float* __restrict__ viw)
{
    int i4 = blockIdx.x * 256 + threadIdx.x;
    const float* src;
    __half* dst;
    if (i4 < 1048576) {
        src = x + (size_t)i4 * 4;
        dst = g_x + (size_t)i4 * 4;
    } else {
        int j = i4 - 1048576;
        int wsel = j >> 18;
        int off = j & 262143;
        const float* wp;
        switch (wsel) {
            case 0: wp = qrw; break;
            case 1: wp = qiw; break;
            case 2: wp = krw; break;
            case 3: wp = kiw; break;
            case 4: wp = vrw; break;
            default: wp = viw; break;
        }
        src = wp + (size_t)off * 4;
        dst = g_w + (size_t)wsel * 1048576 + (size_t)off * 4;
    }
    float4 v = *(const float4*)src;
    uint2 o;
    o.x = h2pack(v.x, v.y);
    o.y = h2pack(v.z, v.w);
    *(uint2*)dst = o;
}

// ---------------------------------------------------------------------------
// Combined output weight (fp16) + fp32 bias.
// ---------------------------------------------------------------------------
__global__ void __launch_bounds__(256) make_wc_kernel(
    const float* __restrict__ orw, const float* __restrict__ oiw,
    const float* __restrict__ orb, const float* __restrict__ oib)
{
    int idx = blockIdx.x * 256 + threadIdx.x;
    int o = idx >> 9;
    int k = (idx & 511) << 2;
    float4 r;
    if (k < 1024) {
        float4 a = *(const float4*)(orw + (size_t)o * 1024 + k);
        float4 b = *(const float4*)(oiw + (size_t)o * 1024 + k);
        r.x = fmaf(0.1f, b.x, a.x); r.y = fmaf(0.1f, b.y, a.y);
        r.z = fmaf(0.1f, b.z, a.z); r.w = fmaf(0.1f, b.w, a.w);
    } else {
        int kk = k - 1024;
        float4 a = *(const float4*)(orw + (size_t)o * 1024 + kk);
        float4 b = *(const float4*)(oiw + (size_t)o * 1024 + kk);
        r.x = fmaf(0.1f, a.x, -b.x); r.y = fmaf(0.1f, a.y, -b.y);
        r.z = fmaf(0.1f, a.z, -b.z); r.w = fmaf(0.1f, a.w, -b.w);
    }
    uint2 ov;
    ov.x = h2pack(r.x, r.y);
    ov.y = h2pack(r.z, r.w);
    *(uint2*)(g_wc + (size_t)o * 2048 + k) = ov;
    if ((idx & 511) == 0)
        g_fb[o] = 1.1f * orb[o] - 0.9f * oib[o];
}

// ---------------------------------------------------------------------------
// Input projections: blockIdx.z = 0/1/2 -> Q/K/V.  fp16 m16n8k16 + ldmatrix.
// BM=128, BN=128, BK=64 halves, double-buffered cp.async.
// All three outputs now share the coalesced [bh][n][128] epilogue.
// ---------------------------------------------------------------------------
__global__ void __launch_bounds__(256, 2) proj_mma_kernel(
    const float* __restrict__ qrb, const float* __restrict__ qib,
    const float* __restrict__ krb, const float* __restrict__ kib,
    const float* __restrict__ vrb, const float* __restrict__ vib)
{
    extern __shared__ uint32_t smw[];
    const uint32_t smem_u = (uint32_t)__cvta_generic_to_shared(smw);

    const int t = threadIdx.x;
    const int w = t >> 5, lane = t & 31, g = lane >> 2, tg = lane & 3;
    const int wm = w >> 2, wn = w & 3;
    const int z = blockIdx.z;
    const int bx = blockIdx.x;
    const int m0 = blockIdx.y * 128;
    const bool imag = bx >= 8;
    const float* bias;
    __half* Out;
    if (z == 0)      { bias = imag ? qib : qrb; Out = g_q; }
    else if (z == 1) { bias = imag ? kib : krb; Out = g_k; }
    else             { bias = imag ? vib : vrb; Out = g_v; }
    const __half* W = g_w + (size_t)(z * 2 + (imag ? 1 : 0)) * 1024 * 1024;
    const int o0 = (bx & 7) * 128;

    const __half* Ag = g_x + (size_t)m0 * 1024;
    const __half* Bg = W + (size_t)o0 * 1024;

    // ldmatrix lane offsets (bytes), row stride 144 B
    const int j = lane >> 3;
    const uint32_t alane = ((j & 1) * 8 + (lane & 7)) * 144 + (j >> 1) * 16;
    const uint32_t blane = ((j >> 1) * 8 + (lane & 7)) * 144 + (j & 1) * 16;

    auto loadAB = [&](int k0, int buf) {
        #pragma unroll
        for (int i = 0; i < 4; i++) {
            int idx = i * 256 + t;
            int row = idx >> 3, c = idx & 7;
            cpa16(smem_u + buf * 18432 + row * 144 + c * 16, Ag + row * 1024 + k0 + c * 8);
            cpa16(smem_u + 36864 + buf * 18432 + row * 144 + c * 16, Bg + row * 1024 + k0 + c * 8);
        }
        CP_COMMIT();
    };

    float acc[4][4][4];
    #pragma unroll
    for (int a = 0; a < 4; a++)
        #pragma unroll
        for (int b = 0; b < 4; b++)
            #pragma unroll
            for (int c = 0; c < 4; c++) acc[a][b][c] = 0.f;

    loadAB(0, 0);

    for (int kt = 0; kt < 16; kt++) {
        CP_WAIT0();
        __syncthreads();
        if (kt + 1 < 16) loadAB((kt + 1) * 64, (kt + 1) & 1);
        const uint32_t ab_u = smem_u + (kt & 1) * 18432 + (64 * wm) * 144 + alane;
        const uint32_t bb_u = smem_u + 36864 + (kt & 1) * 18432 + (32 * wn) * 144 + blane;
        #pragma unroll
        for (int ks = 0; ks < 4; ks++) {
            uint32_t a[4][4];
            #pragma unroll
            for (int mt = 0; mt < 4; mt++)
                ldsm4(a[mt][0], a[mt][1], a[mt][2], a[mt][3],
                      ab_u + mt * (16 * 144) + ks * 32);
            #pragma unroll
            for (int np = 0; np < 2; np++) {
                uint32_t b0, b1, b2, b3;
                ldsm4(b0, b1, b2, b3, bb_u + np * (16 * 144) + ks * 32);
                #pragma unroll
                for (int mt = 0; mt < 4; mt++) {
                    mma16(acc[mt][2 * np],     a[mt][0], a[mt][1], a[mt][2], a[mt][3], b0, b1);
                    mma16(acc[mt][2 * np + 1], a[mt][0], a[mt][1], a[mt][2], a[mt][3], b2, b3);
                }
            }
        }
    }

    // epilogue: coalesced h2 stores into [bh][n][128] for Q, K and V alike
    const int part = imag ? 1 : 0;
    const int ob = o0 + 32 * wn;
    const int hh = ob >> 6;
    #pragma unroll
    for (int mt = 0; mt < 4; mt++) {
        int m = m0 + 64 * wm + 16 * mt + g;
        #pragma unroll
        for (int r = 0; r < 2; r++) {
            int mm = m + 8 * r;
            int b_ = mm >> 11, nn = mm & 2047;
            __half* dst = Out + ((size_t)(b_ * 16 + hh) * 2048 + nn) * 128 + part * 64;
            #pragma unroll
            for (int nt = 0; nt < 4; nt++) {
                int o = ob + 8 * nt + 2 * tg;
                float2 bv = *(const float2*)(bias + o);
                *(uint32_t*)(dst + (o & 63)) =
                    h2pack(acc[mt][nt][2 * r + 0] + bv.x, acc[mt][nt][2 * r + 1] + bv.y);
            }
        }
    }
}

// ---------------------------------------------------------------------------
// Fused complex-magnitude attention, fp16 m16n8k16 + ldmatrix + MUFU softmax.
// Block = 64 queries x one bh; 4 warps; 32-key tiles; 3 CTAs/SM (34KB smem).
// Q fragments in registers; P entirely in registers; K via ldmatrix;
// V stored n-major like K and transposed in-flight with ldmatrix.trans
// (the flash-attention V pattern) -> identical operand values, no d-major
// gmem layout needed.
// Fixed-shift softmax: p = ex2(0.18034*|s| - 11.5416) == exp(0.125*|s| - 8).
// ---------------------------------------------------------------------------
__global__ void __launch_bounds__(128, 3) attn_mma_kernel()
{
    extern __shared__ uint32_t smw[];
    const uint32_t smem_u = (uint32_t)__cvta_generic_to_shared(smw);
    const uint32_t ks0_u = smem_u;
    const uint32_t ks1_u = smem_u + 8704;
    const uint32_t vs0_u = smem_u + 17408;
    const uint32_t vs1_u = smem_u + 26112;

    const int t = threadIdx.x;
    const int w = t >> 5, lane = t & 31, g = lane >> 2, tg = lane & 3;
    const int bh = blockIdx.y;
    const int q0 = blockIdx.x * 64;
    const int qrow = 16 * w;

    const __half* Qg = g_q + ((size_t)bh * 2048 + q0) * 128;
    const __half* Kg = g_k + (size_t)bh * 2048 * 128;
    const __half* Vg = g_v + (size_t)bh * 2048 * 128;

    const int j = lane >> 3;
    const uint32_t klane = (lane & 7) * 272 + (j & 1) * 16 + (j >> 1) * 128;
    // V trans tiles: tile j = key rows 8j..8j+7; d column offset added per nt.
    const uint32_t vlane = (j * 8 + (lane & 7)) * 272;

    // stage Q (64 rows x 256B, dst stride 272B) across the K double buffer
    #pragma unroll
    for (int i = 0; i < 8; i++) {
        int idx = i * 128 + t;
        int row = idx >> 4, c = idx & 15;
        cpa16(ks0_u + row * 272 + c * 16, Qg + row * 128 + c * 8);
    }
    CP_COMMIT();
    CP_WAIT0();
    __syncthreads();

    // Q fragments -> registers (half2 packed)
    uint32_t qr[4][4], qi[4][4];
    #pragma unroll
    for (int ks = 0; ks < 4; ks++) {
        const int col = 8 * ks + tg;
        const uint32_t* r0 = smw + (qrow + g) * 68;
        const uint32_t* r8 = smw + (qrow + g + 8) * 68;
        qr[ks][0] = r0[col];      qr[ks][1] = r8[col];
        qr[ks][2] = r0[col + 4];  qr[ks][3] = r8[col + 4];
        qi[ks][0] = r0[col + 32]; qi[ks][1] = r8[col + 32];
        qi[ks][2] = r0[col + 36]; qi[ks][3] = r8[col + 36];
    }
    __syncthreads();   // done reading staged Q before K(0) overwrites

    auto loadTile = [&](const __half* Tg, int kt, uint32_t su) {
        const __half* Tt = Tg + (size_t)kt * 32 * 128;
        #pragma unroll
        for (int i = 0; i < 4; i++) {
            int idx = i * 128 + t;
            int row = idx >> 4, c = idx & 15;
            cpa16(su + row * 272 + c * 16, Tt + row * 128 + c * 8);
        }
    };

    float O[16][4];
    #pragma unroll
    for (int i = 0; i < 16; i++) { O[i][0] = 0.f; O[i][1] = 0.f; O[i][2] = 0.f; O[i][3] = 0.f; }
    float l0 = 0.f, l1 = 0.f;

    const float K1 = 0.18033688f;   // 0.125 * log2(e)
    const float K2 = -11.541560f;   // -8 * log2(e)

    loadTile(Kg, 0, ks0_u);
    loadTile(Vg, 0, vs0_u);
    CP_COMMIT();

    for (int kt = 0; kt < 64; kt++) {
        CP_WAIT0();
        __syncthreads();
        if (kt + 1 < 64) {
            loadTile(Kg, kt + 1, (kt & 1) ? ks0_u : ks1_u);
            loadTile(Vg, kt + 1, (kt & 1) ? vs0_u : vs1_u);
            CP_COMMIT();
        }
        const uint32_t kb_u = ((kt & 1) ? ks1_u : ks0_u) + klane;
        const uint32_t vb_u = ((kt & 1) ? vs1_u : vs0_u) + vlane;

        float Sr[4][4], Si[4][4];
        #pragma unroll
        for (int i = 0; i < 4; i++) {
            Sr[i][0] = 0.f; Sr[i][1] = 0.f; Sr[i][2] = 0.f; Sr[i][3] = 0.f;
            Si[i][0] = 0.f; Si[i][1] = 0.f; Si[i][2] = 0.f; Si[i][3] = 0.f;
        }

        #pragma unroll
        for (int ks = 0; ks < 4; ks++) {
            const uint32_t ar0 = qr[ks][0], ar1 = qr[ks][1];
            const uint32_t ar2 = qr[ks][2], ar3 = qr[ks][3];
            const uint32_t ai0 = qi[ks][0], ai1 = qi[ks][1];
            const uint32_t ai2 = qi[ks][2], ai3 = qi[ks][3];
            const uint32_t nr0 = ar0 ^ 0x80008000u, nr1 = ar1 ^ 0x80008000u;
            const uint32_t nr2 = ar2 ^ 0x80008000u, nr3 = ar3 ^ 0x80008000u;
            #pragma unroll
            for (int nt = 0; nt < 4; nt++) {
                uint32_t br0, br1, bi0, bi1;
                ldsm4(br0, br1, bi0, bi1, kb_u + nt * 2176 + ks * 32);
                mma16(Sr[nt], ar0, ar1, ar2, ar3, br0, br1);  // qr.kr
                mma16(Sr[nt], ai0, ai1, ai2, ai3, bi0, bi1);  // + qi.ki
                mma16(Si[nt], ai0, ai1, ai2, ai3, br0, br1);  // qi.kr
                mma16(Si[nt], nr0, nr1, nr2, nr3, bi0, bi1);  // - qr.ki
            }
        }

        // magnitude + exp via MUFU; accumulate l; P in registers
        uint32_t pa[4][2];
        #pragma unroll
        for (int nt = 0; nt < 4; nt++) {
            float h0 = fmaf(Si[nt][0], Si[nt][0], Sr[nt][0] * Sr[nt][0]);
            float h1 = fmaf(Si[nt][1], Si[nt][1], Sr[nt][1] * Sr[nt][1]);
            float h2 = fmaf(Si[nt][2], Si[nt][2], Sr[nt][2] * Sr[nt][2]);
            float h3 = fmaf(Si[nt][3], Si[nt][3], Sr[nt][3] * Sr[nt][3]);
            float p0 = ex2_ap(fmaf(sqrt_ap(h0), K1, K2));
            float p1 = ex2_ap(fmaf(sqrt_ap(h1), K1, K2));
            float p2 = ex2_ap(fmaf(sqrt_ap(h2), K1, K2));
            float p3 = ex2_ap(fmaf(sqrt_ap(h3), K1, K2));
            l0 += p0 + p1;
            l1 += p2 + p3;
            pa[nt][0] = h2pack(p0, p1);
            pa[nt][1] = h2pack(p2, p3);
        }

        // O += P @ V  (A = pa in registers; V fragments via ldmatrix.trans:
        //  tiles = key blocks {0-7,8-15,16-23,24-31} at d column 8*nt)
        #pragma unroll
        for (int nt = 0; nt < 16; nt++) {
            uint32_t v0, v1, v2, v3;
            ldsm4t(v0, v1, v2, v3, vb_u + nt * 16);
            mma16(O[nt], pa[0][0], pa[0][1], pa[1][0], pa[1][1], v0, v1);
            mma16(O[nt], pa[2][0], pa[2][1], pa[3][0], pa[3][1], v2, v3);
        }
    }

    // epilogue: divide by row sums, write fp16 merged-head layout into g_z
    l0 += __shfl_xor_sync(0xffffffffu, l0, 1);
    l0 += __shfl_xor_sync(0xffffffffu, l0, 2);
    l1 += __shfl_xor_sync(0xffffffffu, l1, 1);
    l1 += __shfl_xor_sync(0xffffffffu, l1, 2);
    const float inv0 = 1.f / l0, inv1 = 1.f / l1;

    const int b_ = bh >> 4, hh = bh & 15;
    const int q = q0 + qrow + g;
    __half* dst0 = g_z + (size_t)(b_ * 2048 + q) * 2048;
    __half* dst1 = g_z + (size_t)(b_ * 2048 + q + 8) * 2048;
    #pragma unroll
    for (int nt = 0; nt < 16; nt++) {
        int d0 = 8 * nt + 2 * tg;
        int col = (d0 >> 6) * 1024 + hh * 64 + (d0 & 63);
        *(uint32_t*)(dst0 + col) = h2pack(O[nt][0] * inv0, O[nt][1] * inv0);
        *(uint32_t*)(dst1 + col) = h2pack(O[nt][2] * inv1, O[nt][3] * inv1);
    }
}

// ---------------------------------------------------------------------------
// Final GEMM: out[m][o] = sum_k g_z[m][k]*g_wc[o][k] + g_fb[o]
// M=4096, N=1024, K=2048 halves (32 ktiles of 64). ldmatrix fragments.
// ---------------------------------------------------------------------------
__global__ void __launch_bounds__(256, 2) final_mma_kernel(float* __restrict__ Outp)
{
    extern __shared__ uint32_t smw[];
    const uint32_t smem_u = (uint32_t)__cvta_generic_to_shared(smw);

    const int t = threadIdx.x;
    const int w = t >> 5, lane = t & 31, g = lane >> 2, tg = lane & 3;
    const int wm = w >> 2, wn = w & 3;
    const int m0 = blockIdx.y * 128;
    const int o0 = blockIdx.x * 128;

    const __half* Ag = g_z + (size_t)m0 * 2048;
    const __half* Bg = g_wc + (size_t)o0 * 2048;

    const int j = lane >> 3;
    const uint32_t alane = ((j & 1) * 8 + (lane & 7)) * 144 + (j >> 1) * 16;
    const uint32_t blane = ((j >> 1) * 8 + (lane & 7)) * 144 + (j & 1) * 16;

    auto loadAB = [&](int k0, int buf) {
        #pragma unroll
        for (int i = 0; i < 4; i++) {
            int idx = i * 256 + t;
            int row = idx >> 3, c = idx & 7;
            cpa16(smem_u + buf * 18432 + row * 144 + c * 16, Ag + row * 2048 + k0 + c * 8);
            cpa16(smem_u + 36864 + buf * 18432 + row * 144 + c * 16, Bg + row * 2048 + k0 + c * 8);
        }
        CP_COMMIT();
    };

    float acc[4][4][4];
    #pragma unroll
    for (int a = 0; a < 4; a++)
        #pragma unroll
        for (int b = 0; b < 4; b++)
            #pragma unroll
            for (int c = 0; c < 4; c++) acc[a][b][c] = 0.f;

    loadAB(0, 0);

    for (int kt = 0; kt < 32; kt++) {
        CP_WAIT0();
        __syncthreads();
        if (kt + 1 < 32) loadAB((kt + 1) * 64, (kt + 1) & 1);
        const uint32_t ab_u = smem_u + (kt & 1) * 18432 + (64 * wm) * 144 + alane;
        const uint32_t bb_u = smem_u + 36864 + (kt & 1) * 18432 + (32 * wn) * 144 + blane;
        #pragma unroll
        for (int ks = 0; ks < 4; ks++) {
            uint32_t a[4][4];
            #pragma unroll
            for (int mt = 0; mt < 4; mt++)
                ldsm4(a[mt][0], a[mt][1], a[mt][2], a[mt][3],
                      ab_u + mt * (16 * 144) + ks * 32);
            #pragma unroll
            for (int np = 0; np < 2; np++) {
                uint32_t b0, b1, b2, b3;
                ldsm4(b0, b1, b2, b3, bb_u + np * (16 * 144) + ks * 32);
                #pragma unroll
                for (int mt = 0; mt < 4; mt++) {
                    mma16(acc[mt][2 * np],     a[mt][0], a[mt][1], a[mt][2], a[mt][3], b0, b1);
                    mma16(acc[mt][2 * np + 1], a[mt][0], a[mt][1], a[mt][2], a[mt][3], b2, b3);
                }
            }
        }
    }

    const int ob = o0 + 32 * wn;
    #pragma unroll
    for (int mt = 0; mt < 4; mt++) {
        int m = m0 + 64 * wm + 16 * mt + g;
        #pragma unroll
        for (int r = 0; r < 2; r++) {
            int mm = m + 8 * r;
            float* dst = Outp + (size_t)mm * 1024;
            #pragma unroll
            for (int nt = 0; nt < 4; nt++) {
                int o = ob + 8 * nt + 2 * tg;
                float2 fb = *(const float2*)(g_fb + o);
                *(float2*)(dst + o) =
                    make_float2(acc[mt][nt][2 * r + 0] + fb.x,
                                acc[mt][nt][2 * r + 1] + fb.y);
            }
        }
    }
}

// ---------------------------------------------------------------------------
extern "C" void kernel_launch(void* const* d_in, const int* in_sizes, int n_in,
                              void* d_out, int out_size)
{
    const float* x    = (const float*)d_in[0];
    const float* qr_w = (const float*)d_in[1];
    const float* qr_b = (const float*)d_in[2];
    const float* qi_w = (const float*)d_in[3];
    const float* qi_b = (const float*)d_in[4];
    const float* kr_w = (const float*)d_in[5];
    const float* kr_b = (const float*)d_in[6];
    const float* ki_w = (const float*)d_in[7];
    const float* ki_b = (const float*)d_in[8];
    const float* vr_w = (const float*)d_in[9];
    const float* vr_b = (const float*)d_in[10];
    const float* vi_w = (const float*)d_in[11];
    const float* vi_b = (const float*)d_in[12];
    const float* or_w = (const float*)d_in[13];
    const float* or_b = (const float*)d_in[14];
    const float* oi_w = (const float*)d_in[15];
    const float* oi_b = (const float*)d_in[16];
    float* out = (float*)d_out;

    static bool attr_set = false;
    if (!attr_set) {
        cudaFuncSetAttribute(proj_mma_kernel, cudaFuncAttributeMaxDynamicSharedMemorySize, PROJ_SMEM);
        cudaFuncSetAttribute(attn_mma_kernel, cudaFuncAttributeMaxDynamicSharedMemorySize, ATT_SMEM);
        cudaFuncSetAttribute(final_mma_kernel, cudaFuncAttributeMaxDynamicSharedMemorySize, PROJ_SMEM);
        attr_set = true;
    }

    prep_kernel<<<10240, 256>>>(x, qr_w, qi_w, kr_w, ki_w, vr_w, vi_w);
    make_wc_kernel<<<2048, 256>>>(or_w, oi_w, or_b, oi_b);

    proj_mma_kernel<<<dim3(16, 32, 3), 256, PROJ_SMEM>>>(
        qr_b, qi_b, kr_b, ki_b, vr_b, vi_b);

    attn_mma_kernel<<<dim3(32, 32), 128, ATT_SMEM>>>();

    final_mma_kernel<<<dim3(8, 32), 256, PROJ_SMEM>>>(out);
}